// round 6
// baseline (speedup 1.0000x reference)
#include <cuda_runtime.h>
#include <math.h>

#define CIN 2048
#define NB  64
#define NK  32
#define DI  8
#define DO  16
#define EPSQ 1e-7f
#define CPB 64            // c per block
#define CSTRIDE 132       // padded smem stride per c (floats)

typedef unsigned long long ull;

// ---- scratch ----
__device__ float g_xT2[CIN * NB * DI];           // xT2[c][b][j] (4 MB)
__device__ float g_s  [NB * NK * DO];            // s accumulator
__device__ float g_v1 [NB * NK * DO];            // v after iter 1
__device__ float g_a  [(size_t)NK * CIN * NB];   // aT[k][c][b] -> cc (16 MB)
__device__ unsigned g_ctrA;
__device__ unsigned g_ctrE;

// ---- f32x2 helpers ----
__device__ __forceinline__ void fma2(ull& d, ull a, ull b) {
    asm("fma.rn.f32x2 %0, %1, %2, %0;" : "+l"(d) : "l"(a), "l"(b));
}
__device__ __forceinline__ ull pack2(float lo, float hi) {
    ull r; asm("mov.b64 %0, {%1, %2};" : "=l"(r) : "f"(lo), "f"(hi)); return r;
}
__device__ __forceinline__ float2 unpack2(ull v) {
    float2 f; asm("mov.b64 {%0, %1}, %2;" : "=f"(f.x), "=f"(f.y) : "l"(v)); return f;
}

__global__ void k_zero() {
    int t = blockIdx.x * blockDim.x + threadIdx.x;
    if (t < NB * NK * DO) g_s[t] = 0.f;
    if (t == 0) { g_ctrA = 0u; g_ctrE = 0u; }
}

// xT2[(c*64+b)*8+j] = x[b][c][j]
__global__ void k_transpose(const float* __restrict__ x) {
    int idx = blockIdx.x * blockDim.x + threadIdx.x;
    if (idx < CIN * NB * DI) {
        int j = idx & 7, b = (idx >> 3) & 63, c = idx >> 9;
        g_xT2[idx] = __ldg(&x[(b * CIN + c) * DI + j]);
    }
}

// Load W tile [64c][16i][8j] -> sW[c][j][i] with padded stride
__device__ __forceinline__ void load_w_tile(float* sW, const float* __restrict__ W,
                                            int k, int c0) {
    const float4* src = (const float4*)(W + ((size_t)k * CIN + c0) * (DO * DI));
#pragma unroll
    for (int r = 0; r < 8; r++) {
        int idx = threadIdx.x + r * 256;            // 2048 float4
        float4 v = __ldg(&src[idx]);
        int cp = idx >> 5, i = (idx >> 1) & 15, jq = idx & 1;
        float* d = &sW[cp * CSTRIDE + i];
        d[(4 * jq + 0) * 16] = v.x;
        d[(4 * jq + 1) * 16] = v.y;
        d[(4 * jq + 2) * 16] = v.z;
        d[(4 * jq + 3) * 16] = v.w;
    }
}

// block reduce acc[4][8] over 16 c-groups, then atomicAdd into g_s
__device__ __forceinline__ void block_reduce_s(float* red, ull acc[4][8],
                                               int bq, int cg, int k) {
#pragma unroll
    for (int half = 0; half < 2; half++) {
        __syncthreads();
#pragma unroll
        for (int bb = 0; bb < 2; bb++) {
            int bi = 2 * half + bb;
            float* row = &red[(((size_t)cg * 16 + bq) * 2 + bb) * 17];
#pragma unroll
            for (int p = 0; p < 8; p++) {
                float2 f = unpack2(acc[bi][p]);
                row[2 * p]     = f.x;
                row[2 * p + 1] = f.y;
            }
        }
        __syncthreads();
#pragma unroll
        for (int w = 0; w < 2; w++) {
            int u = threadIdx.x + w * 256;          // 512 outputs (bq2,bb2,i)
            int i = u & 15, bb2 = (u >> 4) & 1, bq2 = u >> 5;
            float s = 0.f;
#pragma unroll
            for (int cgi = 0; cgi < 16; cgi++)
                s += red[((cgi * 16 + bq2) * 2 + bb2) * 17 + i];
            int b = bq2 + 16 * (2 * half + bb2);
            atomicAdd(&g_s[(b * NK + k) * DO + i], s);
        }
    }
}

// ---------- Pass A (+ tail: v1 = squash(s/32)) ----------
__global__ void __launch_bounds__(256) k_passA(const float* __restrict__ W) {
    __shared__ __align__(16) float sW[512 * 17];
    int k = blockIdx.y, c0 = blockIdx.x * CPB;
    load_w_tile(sW, W, k, c0);
    __syncthreads();

    int bq = threadIdx.x & 15, cg = threadIdx.x >> 4;
    ull acc[4][8];
#pragma unroll
    for (int bi = 0; bi < 4; bi++)
#pragma unroll
        for (int p = 0; p < 8; p++) acc[bi][p] = 0ull;

#pragma unroll
    for (int it = 0; it < 4; it++) {
        int cl = cg + 16 * it;
        int c  = c0 + cl;
        const ulonglong2* wsv = (const ulonglong2*)&sW[cl * CSTRIDE];
        float xr[4][8];
#pragma unroll
        for (int bi = 0; bi < 4; bi++) {
            const float4* xp = (const float4*)&g_xT2[((size_t)c * NB + (bq + 16 * bi)) * DI];
            float4 a = xp[0], b4 = xp[1];
            xr[bi][0] = a.x;  xr[bi][1] = a.y;  xr[bi][2] = a.z;  xr[bi][3] = a.w;
            xr[bi][4] = b4.x; xr[bi][5] = b4.y; xr[bi][6] = b4.z; xr[bi][7] = b4.w;
        }
#pragma unroll
        for (int j = 0; j < 8; j++) {
            ull xx[4];
#pragma unroll
            for (int bi = 0; bi < 4; bi++) xx[bi] = pack2(xr[bi][j], xr[bi][j]);
#pragma unroll
            for (int q = 0; q < 4; q++) {
                ulonglong2 w2 = wsv[j * 4 + q];
#pragma unroll
                for (int bi = 0; bi < 4; bi++) fma2(acc[bi][2 * q], w2.x, xx[bi]);
#pragma unroll
                for (int bi = 0; bi < 4; bi++) fma2(acc[bi][2 * q + 1], w2.y, xx[bi]);
            }
        }
    }
    block_reduce_s(sW, acc, bq, cg, k);

    // tail: last block computes v1 = squash(s/32)
    __threadfence();
    __syncthreads();
    __shared__ unsigned s_last;
    if (threadIdx.x == 0) s_last = atomicAdd(&g_ctrA, 1u);
    __syncthreads();
    if (s_last == gridDim.x * gridDim.y - 1) {
        for (int t = threadIdx.x; t < NB * NK; t += 256) {
            float s[DO]; float sq = 0.f;
#pragma unroll
            for (int i = 0; i < DO; i++) {
                s[i] = g_s[t * DO + i] * (1.f / 32.f);
                sq += s[i] * s[i];
            }
            float scale = (sq / (1.f + sq)) * rsqrtf(sq + EPSQ);
#pragma unroll
            for (int i = 0; i < DO; i++) g_v1[t * DO + i] = s[i] * scale;
        }
    }
}

// ---------- Pass C: aT[k][c][b] = sum_i u * v1 ----------
__global__ void __launch_bounds__(256) k_passC(const float* __restrict__ W) {
    __shared__ __align__(16) float sW[512 * 17];
    int k = blockIdx.y, c0 = blockIdx.x * CPB;
    load_w_tile(sW, W, k, c0);
    __syncthreads();

    int b0 = threadIdx.x & 31, cg = threadIdx.x >> 5;   // 8 c-groups, b-tile 2
    ull v2[2][8];
#pragma unroll
    for (int bi = 0; bi < 2; bi++) {
        const ull* vp = (const ull*)&g_v1[((b0 + 32 * bi) * NK + k) * DO];
#pragma unroll
        for (int p = 0; p < 8; p++) v2[bi][p] = vp[p];
    }

#pragma unroll
    for (int it = 0; it < 8; it++) {
        int cl = cg + 8 * it;
        int c  = c0 + cl;
        const ulonglong2* wsv = (const ulonglong2*)&sW[cl * CSTRIDE];
        float xr[2][8];
#pragma unroll
        for (int bi = 0; bi < 2; bi++) {
            const float4* xp = (const float4*)&g_xT2[((size_t)c * NB + (b0 + 32 * bi)) * DI];
            float4 a = xp[0], b4 = xp[1];
            xr[bi][0] = a.x;  xr[bi][1] = a.y;  xr[bi][2] = a.z;  xr[bi][3] = a.w;
            xr[bi][4] = b4.x; xr[bi][5] = b4.y; xr[bi][6] = b4.z; xr[bi][7] = b4.w;
        }
        ull u2[2][8];
#pragma unroll
        for (int bi = 0; bi < 2; bi++)
#pragma unroll
            for (int p = 0; p < 8; p++) u2[bi][p] = 0ull;
#pragma unroll
        for (int j = 0; j < 8; j++) {
            ull xx0 = pack2(xr[0][j], xr[0][j]);
            ull xx1 = pack2(xr[1][j], xr[1][j]);
#pragma unroll
            for (int q = 0; q < 4; q++) {
                ulonglong2 w2 = wsv[j * 4 + q];
                fma2(u2[0][2 * q],     w2.x, xx0);
                fma2(u2[1][2 * q],     w2.x, xx1);
                fma2(u2[0][2 * q + 1], w2.y, xx0);
                fma2(u2[1][2 * q + 1], w2.y, xx1);
            }
        }
#pragma unroll
        for (int bi = 0; bi < 2; bi++) {
            ull a2 = 0ull;
#pragma unroll
            for (int p = 0; p < 8; p++) fma2(a2, u2[bi][p], v2[bi][p]);
            float2 af = unpack2(a2);
            g_a[((size_t)k * CIN + c) * NB + (b0 + 32 * bi)] = af.x + af.y;
        }
    }
}

// softmax over k, in place; also re-zeros g_s for pass E
__global__ void k_softmaxZ() {
    int idx = blockIdx.x * blockDim.x + threadIdx.x;
    if (idx < NB * NK * DO) g_s[idx] = 0.f;
    if (idx >= CIN * NB) return;
    float vals[NK]; float mx = -1e30f;
#pragma unroll
    for (int k = 0; k < NK; k++) {
        vals[k] = g_a[(size_t)k * (CIN * NB) + idx];
        mx = fmaxf(mx, vals[k]);
    }
    float sum = 0.f;
#pragma unroll
    for (int k = 0; k < NK; k++) { vals[k] = __expf(vals[k] - mx); sum += vals[k]; }
    float inv = 1.f / sum;
#pragma unroll
    for (int k = 0; k < NK; k++) g_a[(size_t)k * (CIN * NB) + idx] = vals[k] * inv;
}

// ---------- Pass E (+ tail: out = squash(s2)) ----------
__global__ void __launch_bounds__(256) k_passE(const float* __restrict__ W,
                                               float* __restrict__ out) {
    __shared__ __align__(16) float sW[512 * 17];
    int k = blockIdx.y, c0 = blockIdx.x * CPB;
    load_w_tile(sW, W, k, c0);
    __syncthreads();

    int bq = threadIdx.x & 15, cg = threadIdx.x >> 4;
    ull acc[4][8];
#pragma unroll
    for (int bi = 0; bi < 4; bi++)
#pragma unroll
        for (int p = 0; p < 8; p++) acc[bi][p] = 0ull;

#pragma unroll
    for (int it = 0; it < 4; it++) {
        int cl = cg + 16 * it;
        int c  = c0 + cl;
        const ulonglong2* wsv = (const ulonglong2*)&sW[cl * CSTRIDE];
        float xr[4][8];
#pragma unroll
        for (int bi = 0; bi < 4; bi++) {
            int b = bq + 16 * bi;
            float cc = g_a[((size_t)k * CIN + c) * NB + b];
            const float4* xp = (const float4*)&g_xT2[((size_t)c * NB + b) * DI];
            float4 a = xp[0], b4 = xp[1];
            xr[bi][0] = a.x * cc;  xr[bi][1] = a.y * cc;  xr[bi][2] = a.z * cc;  xr[bi][3] = a.w * cc;
            xr[bi][4] = b4.x * cc; xr[bi][5] = b4.y * cc; xr[bi][6] = b4.z * cc; xr[bi][7] = b4.w * cc;
        }
#pragma unroll
        for (int j = 0; j < 8; j++) {
            ull xx[4];
#pragma unroll
            for (int bi = 0; bi < 4; bi++) xx[bi] = pack2(xr[bi][j], xr[bi][j]);
#pragma unroll
            for (int q = 0; q < 4; q++) {
                ulonglong2 w2 = wsv[j * 4 + q];
#pragma unroll
                for (int bi = 0; bi < 4; bi++) fma2(acc[bi][2 * q], w2.x, xx[bi]);
#pragma unroll
                for (int bi = 0; bi < 4; bi++) fma2(acc[bi][2 * q + 1], w2.y, xx[bi]);
            }
        }
    }
    block_reduce_s(sW, acc, bq, cg, k);

    // tail: last block computes out = squash(s2)
    __threadfence();
    __syncthreads();
    __shared__ unsigned s_last;
    if (threadIdx.x == 0) s_last = atomicAdd(&g_ctrE, 1u);
    __syncthreads();
    if (s_last == gridDim.x * gridDim.y - 1) {
        for (int t = threadIdx.x; t < NB * NK; t += 256) {
            float s[DO]; float sq = 0.f;
#pragma unroll
            for (int i = 0; i < DO; i++) { s[i] = g_s[t * DO + i]; sq += s[i] * s[i]; }
            float scale = (sq / (1.f + sq)) * rsqrtf(sq + EPSQ);
#pragma unroll
            for (int i = 0; i < DO; i++) out[t * DO + i] = s[i] * scale;
        }
    }
}

extern "C" void kernel_launch(void* const* d_in, const int* in_sizes, int n_in,
                              void* d_out, int out_size) {
    const float* x = (const float*)d_in[0];
    const float* W = (const float*)d_in[1];
    if (n_in >= 2 && in_sizes[0] == 8388608 && in_sizes[1] == 1048576) {
        const float* t = x; x = W; W = t;   // defensive order swap
    }
    float* out = (float*)d_out;

    dim3 passGrid(CIN / CPB, NK);   // (32, 32)
    dim3 passBlk(256);

    k_transpose<<<(CIN * NB * DI + 255) / 256, 256>>>(x);   // launch 1
    k_zero     <<<128, 256>>>();                            // launch 2
    k_passA    <<<passGrid, passBlk>>>(W);                  // launch 3
    k_passC    <<<passGrid, passBlk>>>(W);                  // launch 4  <- ncu capture
    k_softmaxZ <<<(CIN * NB + 255) / 256, 256>>>();         // launch 5
    k_passE    <<<passGrid, passBlk>>>(W, out);             // launch 6
}

// round 8
// speedup vs baseline: 1.5066x; 1.5066x over previous
#include <cuda_runtime.h>
#include <math.h>

#define CIN 2048
#define NB  64
#define NK  32
#define DI  8
#define DO  16
#define EPSQ 1e-7f
#define CPB 64            // c per block
#define CSTRIDE 132       // smem stride per c for W tile (floats)
#define RSTRIDE 17        // smem stride per b for reduce buffer

typedef unsigned long long ull;

// ---- scratch ----
__device__ float g_xT3[CIN * DI * NB];           // xT3[c][j][b] (4 MB)
__device__ float g_s  [NB * NK * DO];            // s accumulator
__device__ float g_v1 [NB * NK * DO];            // v after iter 1
__device__ float g_a  [(size_t)NK * CIN * NB];   // aT[k][c][b] -> cc (16 MB)

// ---- f32x2 helpers ----
__device__ __forceinline__ void fma2(ull& d, ull a, ull b) {
    asm("fma.rn.f32x2 %0, %1, %2, %0;" : "+l"(d) : "l"(a), "l"(b));
}
__device__ __forceinline__ ull pack2(float lo, float hi) {
    ull r; asm("mov.b64 %0, {%1, %2};" : "=l"(r) : "f"(lo), "f"(hi)); return r;
}
__device__ __forceinline__ float2 unpack2(ull v) {
    float2 f; asm("mov.b64 {%0, %1}, %2;" : "=f"(f.x), "=f"(f.y) : "l"(v)); return f;
}

// xT3[(c*8+j)*64+b] = x[b][c][j]; also zero g_s
__global__ void k_transposeZ(const float* __restrict__ x) {
    int idx = blockIdx.x * blockDim.x + threadIdx.x;
    if (idx < CIN * DI * NB) {
        int b = idx & 63, j = (idx >> 6) & 7, c = idx >> 9;
        g_xT3[idx] = __ldg(&x[(b * CIN + c) * DI + j]);
    }
    if (idx < NB * NK * DO) g_s[idx] = 0.f;
}

// Load W tile [64c][16i][8j] -> sW[c][j][i] (stride CSTRIDE)
__device__ __forceinline__ void load_w_tile(float* sW, const float* __restrict__ W,
                                            int k, int c0) {
    const float4* src = (const float4*)(W + ((size_t)k * CIN + c0) * (DO * DI));
#pragma unroll
    for (int r = 0; r < 8; r++) {
        int idx = threadIdx.x + r * 256;            // 2048 float4
        float4 v = __ldg(&src[idx]);
        int cp = idx >> 5, i = (idx >> 1) & 15, jq = idx & 1;
        float* d = &sW[cp * CSTRIDE + i];
        d[(4 * jq + 0) * 16] = v.x;
        d[(4 * jq + 1) * 16] = v.y;
        d[(4 * jq + 2) * 16] = v.z;
        d[(4 * jq + 3) * 16] = v.w;
    }
}

// block reduce acc[2][8] across 8 warps -> atomicAdd into g_s
__device__ __forceinline__ void block_reduce_s(float* sb, ull acc[2][8],
                                               int w, int b0, int k) {
    __syncthreads();
#pragma unroll
    for (int bi = 0; bi < 2; bi++) {
        float* row = &sb[(w * NB + b0 + bi) * RSTRIDE];
#pragma unroll
        for (int p = 0; p < 8; p++) {
            float2 f = unpack2(acc[bi][p]);
            row[2 * p]     = f.x;
            row[2 * p + 1] = f.y;
        }
    }
    __syncthreads();
#pragma unroll
    for (int r = 0; r < 4; r++) {
        int u = threadIdx.x + 256 * r;              // 1024 outputs (b,i)
        int b = u >> 4, i = u & 15;
        float s = 0.f;
#pragma unroll
        for (int w2 = 0; w2 < 8; w2++)
            s += sb[(w2 * NB + b) * RSTRIDE + i];
        atomicAdd(&g_s[(b * NK + k) * DO + i], s);
    }
}

// ---------- Pass A: s1[b,k,i] = sum_{c,j} W x ----------
__global__ void __launch_bounds__(256) k_passA(const float* __restrict__ W) {
    __shared__ __align__(16) float sb[8704];        // W tile (8448) / reduce (8704)
    int k = blockIdx.y, c0 = blockIdx.x * CPB;
    load_w_tile(sb, W, k, c0);
    __syncthreads();

    int lane = threadIdx.x & 31, w = threadIdx.x >> 5;
    int b0 = 2 * lane;
    ull acc[2][8];
#pragma unroll
    for (int bi = 0; bi < 2; bi++)
#pragma unroll
        for (int p = 0; p < 8; p++) acc[bi][p] = 0ull;

#pragma unroll
    for (int it = 0; it < 8; it++) {
        int cl = 8 * w + it;
        int c  = c0 + cl;
        const ulonglong2* wsv = (const ulonglong2*)&sb[cl * CSTRIDE];
        const float2* xp = ((const float2*)g_xT3) + (size_t)c * (DI * 32) + lane;
        float2 xv[8];
#pragma unroll
        for (int j = 0; j < 8; j++) xv[j] = xp[j * 32];
#pragma unroll
        for (int j = 0; j < 8; j++) {
            ull xx0 = pack2(xv[j].x, xv[j].x);
            ull xx1 = pack2(xv[j].y, xv[j].y);
#pragma unroll
            for (int q = 0; q < 4; q++) {
                ulonglong2 w2 = wsv[j * 4 + q];
                fma2(acc[0][2 * q],     w2.x, xx0);
                fma2(acc[0][2 * q + 1], w2.y, xx0);
                fma2(acc[1][2 * q],     w2.x, xx1);
                fma2(acc[1][2 * q + 1], w2.y, xx1);
            }
        }
    }
    block_reduce_s(sb, acc, w, b0, k);
}

// v1 = squash(s/32)
__global__ void k_squash1() {
    int t = blockIdx.x * blockDim.x + threadIdx.x;
    if (t >= NB * NK) return;
    float s[DO]; float sq = 0.f;
#pragma unroll
    for (int i = 0; i < DO; i++) { s[i] = g_s[t * DO + i] * (1.f / 32.f); sq += s[i] * s[i]; }
    float scale = (sq / (1.f + sq)) * rsqrtf(sq + EPSQ);
#pragma unroll
    for (int i = 0; i < DO; i++) g_v1[t * DO + i] = s[i] * scale;
}

// ---------- Pass C: aT[k][c][b] = sum_i u * v1 ----------
__global__ void __launch_bounds__(256) k_passC(const float* __restrict__ W) {
    __shared__ __align__(16) float sb[8704];
    int k = blockIdx.y, c0 = blockIdx.x * CPB;
    load_w_tile(sb, W, k, c0);
    __syncthreads();

    int lane = threadIdx.x & 31, w = threadIdx.x >> 5;
    int b0 = 2 * lane;
    ull v2[2][8];
#pragma unroll
    for (int bi = 0; bi < 2; bi++) {
        const ull* vp = (const ull*)&g_v1[((b0 + bi) * NK + k) * DO];
#pragma unroll
        for (int p = 0; p < 8; p++) v2[bi][p] = vp[p];
    }

#pragma unroll
    for (int it = 0; it < 8; it++) {
        int cl = 8 * w + it;
        int c  = c0 + cl;
        const ulonglong2* wsv = (const ulonglong2*)&sb[cl * CSTRIDE];
        const float2* xp = ((const float2*)g_xT3) + (size_t)c * (DI * 32) + lane;
        float2 xv[8];
#pragma unroll
        for (int j = 0; j < 8; j++) xv[j] = xp[j * 32];
        ull u2[2][8];
#pragma unroll
        for (int bi = 0; bi < 2; bi++)
#pragma unroll
            for (int p = 0; p < 8; p++) u2[bi][p] = 0ull;
#pragma unroll
        for (int j = 0; j < 8; j++) {
            ull xx0 = pack2(xv[j].x, xv[j].x);
            ull xx1 = pack2(xv[j].y, xv[j].y);
#pragma unroll
            for (int q = 0; q < 4; q++) {
                ulonglong2 w2 = wsv[j * 4 + q];
                fma2(u2[0][2 * q],     w2.x, xx0);
                fma2(u2[0][2 * q + 1], w2.y, xx0);
                fma2(u2[1][2 * q],     w2.x, xx1);
                fma2(u2[1][2 * q + 1], w2.y, xx1);
            }
        }
        ull d0 = 0ull, d1 = 0ull;
#pragma unroll
        for (int p = 0; p < 8; p++) {
            fma2(d0, u2[0][p], v2[0][p]);
            fma2(d1, u2[1][p], v2[1][p]);
        }
        float2 f0 = unpack2(d0), f1 = unpack2(d1);
        ((float2*)&g_a[((size_t)k * CIN + c) * NB])[lane] =
            make_float2(f0.x + f0.y, f1.x + f1.y);
    }
}

// softmax over k at each (c,b), in place; also re-zeros g_s
__global__ void k_softmaxZ() {
    int idx = blockIdx.x * blockDim.x + threadIdx.x;
    if (idx < NB * NK * DO) g_s[idx] = 0.f;
    if (idx >= CIN * NB) return;
    float vals[NK]; float mx = -1e30f;
#pragma unroll
    for (int k = 0; k < NK; k++) {
        vals[k] = g_a[(size_t)k * (CIN * NB) + idx];
        mx = fmaxf(mx, vals[k]);
    }
    float sum = 0.f;
#pragma unroll
    for (int k = 0; k < NK; k++) { vals[k] = __expf(vals[k] - mx); sum += vals[k]; }
    float inv = 1.f / sum;
#pragma unroll
    for (int k = 0; k < NK; k++) g_a[(size_t)k * (CIN * NB) + idx] = vals[k] * inv;
}

// ---------- Pass E: s2[b,k,i] = sum_{c,j} W (cc x) ----------
__global__ void __launch_bounds__(256) k_passE(const float* __restrict__ W) {
    __shared__ __align__(16) float sb[8704];
    int k = blockIdx.y, c0 = blockIdx.x * CPB;
    load_w_tile(sb, W, k, c0);
    __syncthreads();

    int lane = threadIdx.x & 31, w = threadIdx.x >> 5;
    int b0 = 2 * lane;
    ull acc[2][8];
#pragma unroll
    for (int bi = 0; bi < 2; bi++)
#pragma unroll
        for (int p = 0; p < 8; p++) acc[bi][p] = 0ull;

#pragma unroll
    for (int it = 0; it < 8; it++) {
        int cl = 8 * w + it;
        int c  = c0 + cl;
        const ulonglong2* wsv = (const ulonglong2*)&sb[cl * CSTRIDE];
        const float2* xp = ((const float2*)g_xT3) + (size_t)c * (DI * 32) + lane;
        float2 ccv = ((const float2*)&g_a[((size_t)k * CIN + c) * NB])[lane];
        float2 xv[8];
#pragma unroll
        for (int j = 0; j < 8; j++) xv[j] = xp[j * 32];
#pragma unroll
        for (int j = 0; j < 8; j++) {
            ull xx0 = pack2(xv[j].x * ccv.x, xv[j].x * ccv.x);
            ull xx1 = pack2(xv[j].y * ccv.y, xv[j].y * ccv.y);
#pragma unroll
            for (int q = 0; q < 4; q++) {
                ulonglong2 w2 = wsv[j * 4 + q];
                fma2(acc[0][2 * q],     w2.x, xx0);
                fma2(acc[0][2 * q + 1], w2.y, xx0);
                fma2(acc[1][2 * q],     w2.x, xx1);
                fma2(acc[1][2 * q + 1], w2.y, xx1);
            }
        }
    }
    block_reduce_s(sb, acc, w, b0, k);
}

// out = squash(s2)
__global__ void k_squashF(float* __restrict__ out) {
    int t = blockIdx.x * blockDim.x + threadIdx.x;
    if (t >= NB * NK) return;
    float s[DO]; float sq = 0.f;
#pragma unroll
    for (int i = 0; i < DO; i++) { s[i] = g_s[t * DO + i]; sq += s[i] * s[i]; }
    float scale = (sq / (1.f + sq)) * rsqrtf(sq + EPSQ);
#pragma unroll
    for (int i = 0; i < DO; i++) out[t * DO + i] = s[i] * scale;
}

extern "C" void kernel_launch(void* const* d_in, const int* in_sizes, int n_in,
                              void* d_out, int out_size) {
    const float* x = (const float*)d_in[0];
    const float* W = (const float*)d_in[1];
    if (n_in >= 2 && in_sizes[0] == 8388608 && in_sizes[1] == 1048576) {
        const float* t = x; x = W; W = t;   // defensive order swap
    }
    float* out = (float*)d_out;

    dim3 passGrid(CIN / CPB, NK);   // (32, 32)
    dim3 passBlk(256);

    k_transposeZ<<<(CIN * DI * NB + 255) / 256, 256>>>(x);  // 1
    k_passA     <<<passGrid, passBlk>>>(W);                 // 2
    k_squash1   <<<(NB * NK + 127) / 128, 128>>>();         // 3
    k_passC     <<<passGrid, passBlk>>>(W);                 // 4  <- ncu capture
    k_softmaxZ  <<<(CIN * NB + 255) / 256, 256>>>();        // 5
    k_passE     <<<passGrid, passBlk>>>(W);                 // 6
    k_squashF   <<<(NB * NK + 127) / 128, 128>>>(out);      // 7
}

// round 9
// speedup vs baseline: 1.5819x; 1.0499x over previous
#include <cuda_runtime.h>
#include <math.h>

#define CIN 2048
#define NB  64
#define NK  32
#define DI  8
#define DO  16
#define EPSQ 1e-7f
#define CPB 64            // c per block
#define CSTRIDE 132       // smem stride per c for W tile (floats)

typedef unsigned long long ull;

// ---- scratch ----
__device__ float g_xT3[CIN * DI * NB];           // xT3[c][j][b] (4 MB)
__device__ float g_s  [NB * NK * DO];            // s accumulator
__device__ float g_v1 [NB * NK * DO];            // v after iter 1
__device__ float g_a  [(size_t)NK * CIN * NB];   // aT[k][c][b] -> cc (16 MB)

// ---- f32x2 helpers ----
__device__ __forceinline__ void fma2(ull& d, ull a, ull b) {
    asm("fma.rn.f32x2 %0, %1, %2, %0;" : "+l"(d) : "l"(a), "l"(b));
}
__device__ __forceinline__ ull pack2(float lo, float hi) {
    ull r; asm("mov.b64 %0, {%1, %2};" : "=l"(r) : "f"(lo), "f"(hi)); return r;
}
__device__ __forceinline__ float2 unpack2(ull v) {
    float2 f; asm("mov.b64 {%0, %1}, %2;" : "=f"(f.x), "=f"(f.y) : "l"(v)); return f;
}

// xT3[(c*8+j)*64+b] = x[b][c][j]; also zero g_s
__global__ void k_transposeZ(const float* __restrict__ x) {
    int idx = blockIdx.x * blockDim.x + threadIdx.x;
    if (idx < CIN * DI * NB) {
        int b = idx & 63, j = (idx >> 6) & 7, c = idx >> 9;
        g_xT3[idx] = __ldg(&x[(b * CIN + c) * DI + j]);
    }
    if (idx < NB * NK * DO) g_s[idx] = 0.f;
}

// Load W tile [64c][16i][8j] -> sW[c][j][i] (stride CSTRIDE)
__device__ __forceinline__ void load_w_tile(float* sW, const float* __restrict__ W,
                                            int k, int c0) {
    const float4* src = (const float4*)(W + ((size_t)k * CIN + c0) * (DO * DI));
#pragma unroll
    for (int r = 0; r < 8; r++) {
        int idx = threadIdx.x + r * 256;            // 2048 float4
        float4 v = __ldg(&src[idx]);
        int cp = idx >> 5, i = (idx >> 1) & 15, jq = idx & 1;
        float* d = &sW[cp * CSTRIDE + i];
        d[(4 * jq + 0) * 16] = v.x;
        d[(4 * jq + 1) * 16] = v.y;
        d[(4 * jq + 2) * 16] = v.z;
        d[(4 * jq + 3) * 16] = v.w;
    }
}

// block reduce acc[4][4] (4 b, one i-half) across 8 warps -> atomicAdd into g_s
// sb layout: [w 8][b 64][i 16+1pad] = 8704 floats (reuses W-tile buffer)
__device__ __forceinline__ void block_reduce_s(float* sb, ull acc[4][4],
                                               int w, int b0, int ih, int k) {
    __syncthreads();
#pragma unroll
    for (int bi = 0; bi < 4; bi++) {
        float* row = &sb[(w * NB + b0 + bi) * 17 + 8 * ih];
#pragma unroll
        for (int p = 0; p < 4; p++) {
            float2 f = unpack2(acc[bi][p]);
            row[2 * p]     = f.x;
            row[2 * p + 1] = f.y;
        }
    }
    __syncthreads();
#pragma unroll
    for (int r = 0; r < 4; r++) {
        int u = threadIdx.x + 256 * r;              // 1024 outputs (b,i)
        int b = u >> 4, i = u & 15;
        float s = 0.f;
#pragma unroll
        for (int w2 = 0; w2 < 8; w2++)
            s += sb[(w2 * NB + b) * 17 + i];
        atomicAdd(&g_s[(b * NK + k) * DO + i], s);
    }
}

// ---------- Pass A: s1[b,k,i] = sum_{c,j} W x ----------
__global__ void __launch_bounds__(256) k_passA(const float* __restrict__ W) {
    __shared__ __align__(16) float sb[8704];
    int k = blockIdx.y, c0 = blockIdx.x * CPB;
    load_w_tile(sb, W, k, c0);
    __syncthreads();

    int lane = threadIdx.x & 31, w = threadIdx.x >> 5;
    int bq = lane & 15, ih = lane >> 4;
    int b0 = 4 * bq;

    ull acc[4][4];
#pragma unroll
    for (int bi = 0; bi < 4; bi++)
#pragma unroll
        for (int p = 0; p < 4; p++) acc[bi][p] = 0ull;

#pragma unroll
    for (int it = 0; it < 8; it++) {
        int cl = 8 * w + it;
        int c  = c0 + cl;
        const float* wbase = &sb[cl * CSTRIDE + 8 * ih];
        const float4* xbase = (const float4*)&g_xT3[(size_t)c * (DI * NB) + b0];
#pragma unroll
        for (int j = 0; j < 8; j++) {
            float4 xv = xbase[j * 16];              // x[c][j][b0..b0+3]
            ull xx0 = pack2(xv.x, xv.x), xx1 = pack2(xv.y, xv.y);
            ull xx2 = pack2(xv.z, xv.z), xx3 = pack2(xv.w, xv.w);
            const ulonglong2* wp = (const ulonglong2*)(wbase + j * 16);
            ulonglong2 wA = wp[0], wB = wp[1];      // i-pairs 4ih..4ih+3
            fma2(acc[0][0], wA.x, xx0); fma2(acc[0][1], wA.y, xx0);
            fma2(acc[0][2], wB.x, xx0); fma2(acc[0][3], wB.y, xx0);
            fma2(acc[1][0], wA.x, xx1); fma2(acc[1][1], wA.y, xx1);
            fma2(acc[1][2], wB.x, xx1); fma2(acc[1][3], wB.y, xx1);
            fma2(acc[2][0], wA.x, xx2); fma2(acc[2][1], wA.y, xx2);
            fma2(acc[2][2], wB.x, xx2); fma2(acc[2][3], wB.y, xx2);
            fma2(acc[3][0], wA.x, xx3); fma2(acc[3][1], wA.y, xx3);
            fma2(acc[3][2], wB.x, xx3); fma2(acc[3][3], wB.y, xx3);
        }
    }
    block_reduce_s(sb, acc, w, b0, ih, k);
}

// v1 = squash(s/32)
__global__ void k_squash1() {
    int t = blockIdx.x * blockDim.x + threadIdx.x;
    if (t >= NB * NK) return;
    float s[DO]; float sq = 0.f;
#pragma unroll
    for (int i = 0; i < DO; i++) { s[i] = g_s[t * DO + i] * (1.f / 32.f); sq += s[i] * s[i]; }
    float scale = (sq / (1.f + sq)) * rsqrtf(sq + EPSQ);
#pragma unroll
    for (int i = 0; i < DO; i++) g_v1[t * DO + i] = s[i] * scale;
}

// ---------- Pass C: aT[k][c][b] = sum_i u * v1 ----------
__global__ void __launch_bounds__(256) k_passC(const float* __restrict__ W) {
    __shared__ __align__(16) float sb[8704];
    int k = blockIdx.y, c0 = blockIdx.x * CPB;
    load_w_tile(sb, W, k, c0);
    __syncthreads();

    int lane = threadIdx.x & 31, w = threadIdx.x >> 5;
    int bq = lane & 15, ih = lane >> 4;
    int b0 = 4 * bq;

    ull v2[4][4];
#pragma unroll
    for (int bi = 0; bi < 4; bi++) {
        const ull* vp = (const ull*)&g_v1[((b0 + bi) * NK + k) * DO + 8 * ih];
#pragma unroll
        for (int p = 0; p < 4; p++) v2[bi][p] = vp[p];
    }

#pragma unroll
    for (int it = 0; it < 8; it++) {
        int cl = 8 * w + it;
        int c  = c0 + cl;
        const float* wbase = &sb[cl * CSTRIDE + 8 * ih];
        const float4* xbase = (const float4*)&g_xT3[(size_t)c * (DI * NB) + b0];

        ull u2[4][4];
#pragma unroll
        for (int bi = 0; bi < 4; bi++)
#pragma unroll
            for (int p = 0; p < 4; p++) u2[bi][p] = 0ull;

#pragma unroll
        for (int j = 0; j < 8; j++) {
            float4 xv = xbase[j * 16];
            ull xx0 = pack2(xv.x, xv.x), xx1 = pack2(xv.y, xv.y);
            ull xx2 = pack2(xv.z, xv.z), xx3 = pack2(xv.w, xv.w);
            const ulonglong2* wp = (const ulonglong2*)(wbase + j * 16);
            ulonglong2 wA = wp[0], wB = wp[1];
            fma2(u2[0][0], wA.x, xx0); fma2(u2[0][1], wA.y, xx0);
            fma2(u2[0][2], wB.x, xx0); fma2(u2[0][3], wB.y, xx0);
            fma2(u2[1][0], wA.x, xx1); fma2(u2[1][1], wA.y, xx1);
            fma2(u2[1][2], wB.x, xx1); fma2(u2[1][3], wB.y, xx1);
            fma2(u2[2][0], wA.x, xx2); fma2(u2[2][1], wA.y, xx2);
            fma2(u2[2][2], wB.x, xx2); fma2(u2[2][3], wB.y, xx2);
            fma2(u2[3][0], wA.x, xx3); fma2(u2[3][1], wA.y, xx3);
            fma2(u2[3][2], wB.x, xx3); fma2(u2[3][3], wB.y, xx3);
        }
        float a[4];
#pragma unroll
        for (int bi = 0; bi < 4; bi++) {
            ull d = 0ull;
#pragma unroll
            for (int p = 0; p < 4; p++) fma2(d, u2[bi][p], v2[bi][p]);
            float2 f = unpack2(d);
            a[bi] = f.x + f.y;                      // partial over this i-half
        }
        // combine the two i-halves
#pragma unroll
        for (int bi = 0; bi < 4; bi++)
            a[bi] += __shfl_xor_sync(0xFFFFFFFFu, a[bi], 16);
        if (ih == 0) {
            float4* dst = (float4*)&g_a[((size_t)k * CIN + c) * NB + b0];
            *dst = make_float4(a[0], a[1], a[2], a[3]);
        }
    }
}

// softmax over k at each (c,b), in place; also re-zeros g_s
__global__ void k_softmaxZ() {
    int idx = blockIdx.x * blockDim.x + threadIdx.x;
    if (idx < NB * NK * DO) g_s[idx] = 0.f;
    if (idx >= CIN * NB) return;
    float vals[NK]; float mx = -1e30f;
#pragma unroll
    for (int k = 0; k < NK; k++) {
        vals[k] = g_a[(size_t)k * (CIN * NB) + idx];
        mx = fmaxf(mx, vals[k]);
    }
    float sum = 0.f;
#pragma unroll
    for (int k = 0; k < NK; k++) { vals[k] = __expf(vals[k] - mx); sum += vals[k]; }
    float inv = 1.f / sum;
#pragma unroll
    for (int k = 0; k < NK; k++) g_a[(size_t)k * (CIN * NB) + idx] = vals[k] * inv;
}

// ---------- Pass E: s2[b,k,i] = sum_{c,j} W (cc x) ----------
__global__ void __launch_bounds__(256) k_passE(const float* __restrict__ W) {
    __shared__ __align__(16) float sb[8704];
    int k = blockIdx.y, c0 = blockIdx.x * CPB;
    load_w_tile(sb, W, k, c0);
    __syncthreads();

    int lane = threadIdx.x & 31, w = threadIdx.x >> 5;
    int bq = lane & 15, ih = lane >> 4;
    int b0 = 4 * bq;

    ull acc[4][4];
#pragma unroll
    for (int bi = 0; bi < 4; bi++)
#pragma unroll
        for (int p = 0; p < 4; p++) acc[bi][p] = 0ull;

#pragma unroll
    for (int it = 0; it < 8; it++) {
        int cl = 8 * w + it;
        int c  = c0 + cl;
        const float* wbase = &sb[cl * CSTRIDE + 8 * ih];
        const float4* xbase = (const float4*)&g_xT3[(size_t)c * (DI * NB) + b0];
        float4 cc = *(const float4*)&g_a[((size_t)k * CIN + c) * NB + b0];
#pragma unroll
        for (int j = 0; j < 8; j++) {
            float4 xv = xbase[j * 16];
            float m0 = xv.x * cc.x, m1 = xv.y * cc.y;
            float m2 = xv.z * cc.z, m3 = xv.w * cc.w;
            ull xx0 = pack2(m0, m0), xx1 = pack2(m1, m1);
            ull xx2 = pack2(m2, m2), xx3 = pack2(m3, m3);
            const ulonglong2* wp = (const ulonglong2*)(wbase + j * 16);
            ulonglong2 wA = wp[0], wB = wp[1];
            fma2(acc[0][0], wA.x, xx0); fma2(acc[0][1], wA.y, xx0);
            fma2(acc[0][2], wB.x, xx0); fma2(acc[0][3], wB.y, xx0);
            fma2(acc[1][0], wA.x, xx1); fma2(acc[1][1], wA.y, xx1);
            fma2(acc[1][2], wB.x, xx1); fma2(acc[1][3], wB.y, xx1);
            fma2(acc[2][0], wA.x, xx2); fma2(acc[2][1], wA.y, xx2);
            fma2(acc[2][2], wB.x, xx2); fma2(acc[2][3], wB.y, xx2);
            fma2(acc[3][0], wA.x, xx3); fma2(acc[3][1], wA.y, xx3);
            fma2(acc[3][2], wB.x, xx3); fma2(acc[3][3], wB.y, xx3);
        }
    }
    block_reduce_s(sb, acc, w, b0, ih, k);
}

// out = squash(s2)
__global__ void k_squashF(float* __restrict__ out) {
    int t = blockIdx.x * blockDim.x + threadIdx.x;
    if (t >= NB * NK) return;
    float s[DO]; float sq = 0.f;
#pragma unroll
    for (int i = 0; i < DO; i++) { s[i] = g_s[t * DO + i]; sq += s[i] * s[i]; }
    float scale = (sq / (1.f + sq)) * rsqrtf(sq + EPSQ);
#pragma unroll
    for (int i = 0; i < DO; i++) out[t * DO + i] = s[i] * scale;
}

extern "C" void kernel_launch(void* const* d_in, const int* in_sizes, int n_in,
                              void* d_out, int out_size) {
    const float* x = (const float*)d_in[0];
    const float* W = (const float*)d_in[1];
    if (n_in >= 2 && in_sizes[0] == 8388608 && in_sizes[1] == 1048576) {
        const float* t = x; x = W; W = t;   // defensive order swap
    }
    float* out = (float*)d_out;

    dim3 passGrid(CIN / CPB, NK);   // (32, 32)
    dim3 passBlk(256);

    k_transposeZ<<<(CIN * DI * NB + 255) / 256, 256>>>(x);  // 1
    k_passA     <<<passGrid, passBlk>>>(W);                 // 2
    k_squash1   <<<(NB * NK + 127) / 128, 128>>>();         // 3
    k_passC     <<<passGrid, passBlk>>>(W);                 // 4  <- ncu capture
    k_softmaxZ  <<<(CIN * NB + 255) / 256, 256>>>();        // 5
    k_passE     <<<passGrid, passBlk>>>(W);                 // 6
    k_squashF   <<<(NB * NK + 127) / 128, 128>>>(out);      // 7
}